// round 13
// baseline (speedup 1.0000x reference)
#include <cuda_runtime.h>
#include <cuda_fp16.h>
#include <cstdint>
#include <math.h>

#define BS 32
#define KP 1000
#define KG 100
#define NC 80
#define NC8 (NC/8)             // 10 uint4 (8 halves) per alpha row
#define QT 128                 // qq tile edge
#define NTQ 8                  // ceil(KP/QT)
#define NPAIR (NTQ*(NTQ+1)/2)  // 36 triangular tile pairs
#define PQ_BLOCKS 4
#define FUSED_X (NPAIR + PQ_BLOCKS + 1)
#define APITCH 88              // row pitch in halves (conflict-free, 16B-aligned rows)
#define ROWB (APITCH*2)        // 176 bytes per row

// dynamic smem layout (bytes)
#define SM_A     0
#define SM_B     (QT*ROWB)                // 22528
#define SM_GI    (2*QT*ROWB)              // 45056
#define SM_GJ    (SM_GI + QT*16)          // 47104
#define SM_RED   (SM_GJ + QT*16)          // 49152
#define SM_TOTAL (SM_RED + 64)            // 49216

__device__ __half g_alpha[BS*KP*NC];
__device__ double g_qq[BS][NPAIR];
__device__ double g_pq[BS][PQ_BLOCKS];
__device__ double g_pp[BS];

__device__ __forceinline__ uint32_t smem_u32(const void* p) {
    uint32_t a;
    asm("{ .reg .u64 t; cvta.to.shared.u64 t, %1; cvt.u32.u64 %0, t; }" : "=r"(a) : "l"(p));
    return a;
}

__device__ __forceinline__ float warp_sum(float v) {
    #pragma unroll
    for (int o = 16; o; o >>= 1) v += __shfl_xor_sync(0xffffffffu, v, o);
    return v;
}

__device__ __forceinline__ double warp_sum_d(double v) {
    #pragma unroll
    for (int o = 16; o; o >>= 1) v += __shfl_xor_sync(0xffffffffu, v, o);
    return v;
}

// fp16-accumulator MMA: D,C are 2x f16x2 regs.
#define MMA_F16ACC(d, a, bq) \
    asm volatile("mma.sync.aligned.m16n8k16.row.col.f16.f16.f16.f16 " \
        "{%0,%1}, {%2,%3,%4,%5}, {%6,%7}, {%0,%1};" \
        : "+r"((d)[0]), "+r"((d)[1]) \
        : "r"((a)[0]), "r"((a)[1]), "r"((a)[2]), "r"((a)[3]), \
          "r"((bq)[0]), "r"((bq)[1]))

#define LDSM_X4(r0, r1, r2, r3, addr) \
    asm volatile("ldmatrix.sync.aligned.m8n8.x4.shared.b16 {%0,%1,%2,%3}, [%4];" \
        : "=r"(r0), "=r"(r1), "=r"(r2), "=r"(r3) : "r"(addr))

// Gaussian overlap (1/(2pi) cancels in the final log combination):
// g = exp2(C*q) * r,  C = -log2(e)/2,  q = (dx^2*sy + dy^2*sx)/(sx*sy),  r = rsqrt(sx*sy)
#define GAUSS_C (-0.7213475204444817f)
__device__ __forceinline__ float gauss_pair(float4 P, float4 Q) {
    float sx = P.z + Q.z, sy = P.w + Q.w;
    float dx = P.x - Q.x, dy = P.y - Q.y;
    float r = rsqrtf(sx * sy);
    float rrc = r * r * GAUSS_C;
    float q = fmaf(dy * dy, sx, dx * dx * sy) * rrc;
    return exp2f(q) * r;
}

// ---------------------------------------------------------------------------
// pred_alpha = sigmoid(logit[80]) * softmax(logit[0:80]); 2 rows per warp
// for ILP. Logits ~N(0,1): exp() cannot overflow fp32 -> no max-subtraction.
// ---------------------------------------------------------------------------
__global__ __launch_bounds__(256) void alpha_kernel(const float* __restrict__ labels) {
    int rowBase = (blockIdx.x * 8 + threadIdx.y) * 2;
    if (rowBase >= BS * KP) return;
    int lane = threadIdx.x;
    const float* L0 = labels + (long long)rowBase * (NC + 1);
    const float* L1 = L0 + (NC + 1);

    float a0 = __expf(L0[lane]);
    float b0 = __expf(L1[lane]);
    float a1 = __expf(L0[lane + 32]);
    float b1 = __expf(L1[lane + 32]);
    float a2 = (lane < 16) ? __expf(L0[lane + 64]) : 0.f;
    float b2 = (lane < 16) ? __expf(L1[lane + 64]) : 0.f;

    float sa = a0 + a1 + a2;
    float sb = b0 + b1 + b2;
    #pragma unroll
    for (int o = 16; o; o >>= 1) {
        sa += __shfl_xor_sync(0xffffffffu, sa, o);
        sb += __shfl_xor_sync(0xffffffffu, sb, o);
    }

    float siga = 1.f / (1.f + __expf(-L0[NC]));
    float sigb = 1.f / (1.f + __expf(-L1[NC]));
    float sc_a = siga / sa;
    float sc_b = sigb / sb;

    __half* o0 = g_alpha + (long long)rowBase * NC;
    __half* o1 = o0 + NC;
    o0[lane]      = __float2half_rn(a0 * sc_a);
    o1[lane]      = __float2half_rn(b0 * sc_b);
    o0[lane + 32] = __float2half_rn(a1 * sc_a);
    o1[lane + 32] = __float2half_rn(b1 * sc_b);
    if (lane < 16) {
        o0[lane + 64] = __float2half_rn(a2 * sc_a);
        o1[lane + 64] = __float2half_rn(b2 * sc_b);
    }
}

// ---------------------------------------------------------------------------
// Fused: bx < NPAIR -> qq 128x128 tile pair via fp16 mma.sync (f16 accum)
//        bx < NPAIR+PQ_BLOCKS -> pq chunk ; else -> pp
// ---------------------------------------------------------------------------
__global__ __launch_bounds__(256, 3)
void fused_kernel(const float* __restrict__ pred_bboxes,
                  const float* __restrict__ gt_bboxes,
                  const int* __restrict__ gt_labels) {
    extern __shared__ char smem[];
    int b = blockIdx.y;
    int bx = blockIdx.x;
    int tid = threadIdx.x;
    float* red = (float*)(smem + SM_RED);

    if (bx < NPAIR) {
        // ================= qq via fp16 tensor cores =================
        int p = bx, ti = 0;
        while (p >= NTQ - ti) { p -= NTQ - ti; ti++; }
        int tj = ti + p;

        float4* sGi = (float4*)(smem + SM_GI);
        float4* sGj = (float4*)(smem + SM_GJ);

        // Stage fp16 alphas (8 halves per uint4).
        const uint4* alpha8 = (const uint4*)(g_alpha + (long long)b * KP * NC);
        for (int idx = tid; idx < 2 * QT * NC8; idx += 256) {
            int t = (idx >= QT * NC8);
            int l = idx - t * QT * NC8;
            int r = l / NC8, c8 = l - r * NC8;
            int g = (t ? tj : ti) * QT + r;
            uint4 v = (g < KP) ? alpha8[g * NC8 + c8] : make_uint4(0u, 0u, 0u, 0u);
            *(uint4*)(smem + (t ? SM_B : SM_A) + r * ROWB + c8 * 16) = v;
        }
        const float4* bb4 = (const float4*)pred_bboxes;
        for (int r = tid; r < QT; r += 256) {
            int gi = ti * QT + r;
            float4 u = (gi < KP) ? bb4[b * KP + gi] : make_float4(0.f, 0.f, 4.f, 4.f);
            sGi[r] = make_float4(u.x, u.y, u.z * u.z * 0.25f, u.w * u.w * 0.25f);
            int gj = tj * QT + r;
            float4 v = (gj < KP) ? bb4[b * KP + gj] : make_float4(0.f, 0.f, 4.f, 4.f);
            sGj[r] = make_float4(v.x, v.y, v.z * v.z * 0.25f, v.w * v.w * 0.25f);
        }
        __syncthreads();

        int wid = tid >> 5, lane = tid & 31;
        int g = lane >> 2, t = lane & 3;
        int mBase = (wid & 1) * 64;
        int nBase = (wid >> 1) * 32;

        // ldmatrix addressing: lanes 0-15 -> rows (k lo), 16-31 -> rows (k hi)
        int laneRow = lane & 15;
        int laneHi = (lane >> 4) & 1;
        uint32_t sbase = smem_u32(smem);
        uint32_t aAddr = sbase + SM_A + (mBase + laneRow) * ROWB + laneHi * 16;
        uint32_t bAddr = sbase + SM_B + (nBase + laneRow) * ROWB + laneHi * 16;

        uint32_t acc[4][4][2];
        #pragma unroll
        for (int mi = 0; mi < 4; mi++)
            #pragma unroll
            for (int ni = 0; ni < 4; ni++) { acc[mi][ni][0] = 0u; acc[mi][ni][1] = 0u; }

        #pragma unroll
        for (int k0 = 0; k0 < 5; k0++) {    // K=80, 16 per MMA
            uint32_t a[4][4], bf[4][2];
            #pragma unroll
            for (int mi = 0; mi < 4; mi++)
                LDSM_X4(a[mi][0], a[mi][1], a[mi][2], a[mi][3],
                        aAddr + mi * 16 * ROWB + k0 * 32);
            #pragma unroll
            for (int p2 = 0; p2 < 2; p2++) {
                uint32_t r0, r1, r2, r3;
                LDSM_X4(r0, r1, r2, r3, bAddr + p2 * 16 * ROWB + k0 * 32);
                bf[2 * p2][0] = r0; bf[2 * p2 + 1][0] = r1;
                bf[2 * p2][1] = r2; bf[2 * p2 + 1][1] = r3;
            }
            #pragma unroll
            for (int mi = 0; mi < 4; mi++)
                #pragma unroll
                for (int ni = 0; ni < 4; ni++)
                    MMA_F16ACC(acc[mi][ni], a[mi], bf[ni]);
        }

        // Epilogue: W[row][col] * gauss(row, col).
        // P/Q tables register-cached: 16 LDS.128/thread instead of 72.
        float4 P0[4], P1[4], Qc[8];
        #pragma unroll
        for (int mi = 0; mi < 4; mi++) {
            P0[mi] = sGi[mBase + mi * 16 + g];
            P1[mi] = sGi[mBase + mi * 16 + g + 8];
        }
        #pragma unroll
        for (int ni = 0; ni < 4; ni++) {
            Qc[ni * 2]     = sGj[nBase + ni * 8 + t * 2];
            Qc[ni * 2 + 1] = sGj[nBase + ni * 8 + t * 2 + 1];
        }
        float tsum = 0.f;
        #pragma unroll
        for (int mi = 0; mi < 4; mi++) {
            #pragma unroll
            for (int ni = 0; ni < 4; ni++) {
                float2 w01 = __half22float2(*(const __half2*)&acc[mi][ni][0]);
                float2 w23 = __half22float2(*(const __half2*)&acc[mi][ni][1]);
                tsum = fmaf(w01.x, gauss_pair(P0[mi], Qc[ni * 2]), tsum);
                tsum = fmaf(w01.y, gauss_pair(P0[mi], Qc[ni * 2 + 1]), tsum);
                tsum = fmaf(w23.x, gauss_pair(P1[mi], Qc[ni * 2]), tsum);
                tsum = fmaf(w23.y, gauss_pair(P1[mi], Qc[ni * 2 + 1]), tsum);
            }
        }

        float s = warp_sum(tsum);
        if (lane == 0) red[wid] = s;
        __syncthreads();
        if (tid < 32) {
            float x = (tid < 8) ? red[tid] : 0.f;
            x = warp_sum(x);
            if (tid == 0) {
                float mult = (ti == tj) ? 1.f : 2.f;
                g_qq[b][bx] = (double)(x * mult);
            }
        }
    } else {
        // ================= pq / pp =================
        float4* sG = (float4*)(smem);
        int* sL = (int*)(smem + KG * 16);
        for (int i = tid; i < KG; i += 256) {
            float4 u = ((const float4*)gt_bboxes)[b * KG + i];
            sG[i] = make_float4(u.x, u.y, u.z * u.z * 0.25f, u.w * u.w * 0.25f);
            sL[i] = gt_labels[b * KG + i];
        }
        __syncthreads();

        float acc = 0.f;
        int chunk = bx - NPAIR;
        if (chunk < PQ_BLOCKS) {
            int j = chunk * 256 + tid;
            if (j < KP) {
                float4 u = ((const float4*)pred_bboxes)[b * KP + j];
                float4 Q = make_float4(u.x, u.y, u.z * u.z * 0.25f, u.w * u.w * 0.25f);
                const __half* arow = g_alpha + ((long long)b * KP + j) * NC;
                #pragma unroll 4
                for (int i = 0; i < KG; i++) {
                    float w = __half2float(__ldg(arow + sL[i]));
                    acc = fmaf(w, gauss_pair(sG[i], Q), acc);
                }
            }
        } else {
            for (int idx = tid; idx < KG * KG; idx += 256) {
                int i = idx / KG, j = idx - i * KG;
                if (sL[i] == sL[j]) acc += gauss_pair(sG[i], sG[j]);
            }
        }
        float s = warp_sum(acc);
        if ((tid & 31) == 0) red[tid >> 5] = s;
        __syncthreads();
        if (tid < 32) {
            float x = (tid < 8) ? red[tid] : 0.f;
            x = warp_sum(x);
            if (tid == 0) {
                if (chunk < PQ_BLOCKS) g_pq[b][chunk] = (double)x;
                else g_pp[b] = (double)x;
            }
        }
    }
}

// ---------------------------------------------------------------------------
// final: loss = -sum_b [2 log(pq_b) - log(pp_b) - log(qq_b)].
// One warp per image: lanes stride the 136 qq slots in parallel (5 loads per
// lane instead of a 141-load serial chain -> ~6x faster than 32-thread version).
// ---------------------------------------------------------------------------
__global__ __launch_bounds__(1024) void final_kernel(float* __restrict__ out) {
    __shared__ double sv[BS];
    int b = threadIdx.y;     // 32 warps, one per image
    int lane = threadIdx.x;

    double qq = 0.0;
    #pragma unroll
    for (int s = lane; s < NPAIR; s += 32) qq += g_qq[b][s];
    double pq = (lane < PQ_BLOCKS) ? g_pq[b][lane] : 0.0;

    qq = warp_sum_d(qq);
    pq = warp_sum_d(pq);

    if (lane == 0) {
        double pp = g_pp[b];
        sv[b] = 2.0 * log(pq) - log(pp) - log(qq);
    }
    __syncthreads();
    if (threadIdx.y == 0) {
        double v = sv[lane];
        v = warp_sum_d(v);
        if (lane == 0) out[0] = (float)(-v);
    }
}

extern "C" void kernel_launch(void* const* d_in, const int* in_sizes, int n_in,
                              void* d_out, int out_size) {
    const float* pred_bboxes = (const float*)d_in[0];
    const float* pred_labels = (const float*)d_in[1];
    const float* gt_bboxes   = (const float*)d_in[2];
    const int*   gt_labels   = (const int*)d_in[3];
    (void)in_sizes; (void)n_in; (void)out_size;

    cudaFuncSetAttribute(fused_kernel, cudaFuncAttributeMaxDynamicSharedMemorySize, SM_TOTAL);

    alpha_kernel<<<(BS * KP + 15) / 16, dim3(32, 8)>>>(pred_labels);
    fused_kernel<<<dim3(FUSED_X, BS), 256, SM_TOTAL>>>(pred_bboxes, gt_bboxes, gt_labels);
    final_kernel<<<1, dim3(32, 32)>>>((float*)d_out);
}

// round 14
// speedup vs baseline: 1.0040x; 1.0040x over previous
#include <cuda_runtime.h>
#include <cuda_fp16.h>
#include <cstdint>
#include <math.h>

#define BS 32
#define KP 1000
#define KG 100
#define NC 80
#define NC8 (NC/8)             // 10 uint4 (8 halves) per alpha row
#define QT 128                 // qq tile edge
#define NTQ 8                  // ceil(KP/QT)
#define NPAIR (NTQ*(NTQ+1)/2)  // 36 triangular tile pairs
#define PQ_BLOCKS 4
#define FUSED_X (NPAIR + PQ_BLOCKS + 1)
#define APITCH 88              // row pitch in halves (conflict-free, 16B-aligned rows)
#define ROWB (APITCH*2)        // 176 bytes per row

// dynamic smem layout (bytes)
#define SM_A     0
#define SM_B     (QT*ROWB)                // 22528
#define SM_GI    (2*QT*ROWB)              // 45056
#define SM_GJ    (SM_GI + QT*16)          // 47104
#define SM_RED   (SM_GJ + QT*16)          // 49152
#define SM_TOTAL (SM_RED + 64)            // 49216

__device__ __half g_alpha[BS*KP*NC];
__device__ double g_qq[BS][NPAIR];
__device__ double g_pq[BS][PQ_BLOCKS];
__device__ double g_pp[BS];

__device__ __forceinline__ uint32_t smem_u32(const void* p) {
    uint32_t a;
    asm("{ .reg .u64 t; cvta.to.shared.u64 t, %1; cvt.u32.u64 %0, t; }" : "=r"(a) : "l"(p));
    return a;
}

__device__ __forceinline__ float warp_sum(float v) {
    #pragma unroll
    for (int o = 16; o; o >>= 1) v += __shfl_xor_sync(0xffffffffu, v, o);
    return v;
}

__device__ __forceinline__ double warp_sum_d(double v) {
    #pragma unroll
    for (int o = 16; o; o >>= 1) v += __shfl_xor_sync(0xffffffffu, v, o);
    return v;
}

// fp16-accumulator MMA: D,C are 2x f16x2 regs.
#define MMA_F16ACC(d, a, bq) \
    asm volatile("mma.sync.aligned.m16n8k16.row.col.f16.f16.f16.f16 " \
        "{%0,%1}, {%2,%3,%4,%5}, {%6,%7}, {%0,%1};" \
        : "+r"((d)[0]), "+r"((d)[1]) \
        : "r"((a)[0]), "r"((a)[1]), "r"((a)[2]), "r"((a)[3]), \
          "r"((bq)[0]), "r"((bq)[1]))

#define LDSM_X4(r0, r1, r2, r3, addr) \
    asm volatile("ldmatrix.sync.aligned.m8n8.x4.shared.b16 {%0,%1,%2,%3}, [%4];" \
        : "=r"(r0), "=r"(r1), "=r"(r2), "=r"(r3) : "r"(addr))

// Gaussian overlap (1/(2pi) cancels in the final log combination):
// g = exp2(C*q) * r,  C = -log2(e)/2,  q = (dx^2*sy + dy^2*sx)/(sx*sy),  r = rsqrt(sx*sy)
#define GAUSS_C (-0.7213475204444817f)
__device__ __forceinline__ float gauss_pair(float4 P, float4 Q) {
    float sx = P.z + Q.z, sy = P.w + Q.w;
    float dx = P.x - Q.x, dy = P.y - Q.y;
    float r = rsqrtf(sx * sy);
    float rrc = r * r * GAUSS_C;
    float q = fmaf(dy * dy, sx, dx * dx * sy) * rrc;
    return exp2f(q) * r;
}

// ---------------------------------------------------------------------------
// pred_alpha = sigmoid(logit[80]) * softmax(logit[0:80]); 2 rows per warp
// for ILP. Logits ~N(0,1): exp() cannot overflow fp32 -> no max-subtraction.
// ---------------------------------------------------------------------------
__global__ __launch_bounds__(256) void alpha_kernel(const float* __restrict__ labels) {
    int rowBase = (blockIdx.x * 8 + threadIdx.y) * 2;
    if (rowBase >= BS * KP) return;
    int lane = threadIdx.x;
    const float* L0 = labels + (long long)rowBase * (NC + 1);
    const float* L1 = L0 + (NC + 1);

    float a0 = __expf(L0[lane]);
    float b0 = __expf(L1[lane]);
    float a1 = __expf(L0[lane + 32]);
    float b1 = __expf(L1[lane + 32]);
    float a2 = (lane < 16) ? __expf(L0[lane + 64]) : 0.f;
    float b2 = (lane < 16) ? __expf(L1[lane + 64]) : 0.f;

    float sa = a0 + a1 + a2;
    float sb = b0 + b1 + b2;
    #pragma unroll
    for (int o = 16; o; o >>= 1) {
        sa += __shfl_xor_sync(0xffffffffu, sa, o);
        sb += __shfl_xor_sync(0xffffffffu, sb, o);
    }

    float siga = 1.f / (1.f + __expf(-L0[NC]));
    float sigb = 1.f / (1.f + __expf(-L1[NC]));
    float sc_a = siga / sa;
    float sc_b = sigb / sb;

    __half* o0 = g_alpha + (long long)rowBase * NC;
    __half* o1 = o0 + NC;
    o0[lane]      = __float2half_rn(a0 * sc_a);
    o1[lane]      = __float2half_rn(b0 * sc_b);
    o0[lane + 32] = __float2half_rn(a1 * sc_a);
    o1[lane + 32] = __float2half_rn(b1 * sc_b);
    if (lane < 16) {
        o0[lane + 64] = __float2half_rn(a2 * sc_a);
        o1[lane + 64] = __float2half_rn(b2 * sc_b);
    }
}

// ---------------------------------------------------------------------------
// Fused (identical to the 47.6us R9 version): qq via fp16 mma.sync with
// ldmatrix fragment loads, smem-read epilogue (register-caching the P/Q
// tables spills at the 3-block reg cap -> keep LDS reads).
// ---------------------------------------------------------------------------
__global__ __launch_bounds__(256, 3)
void fused_kernel(const float* __restrict__ pred_bboxes,
                  const float* __restrict__ gt_bboxes,
                  const int* __restrict__ gt_labels) {
    extern __shared__ char smem[];
    int b = blockIdx.y;
    int bx = blockIdx.x;
    int tid = threadIdx.x;
    float* red = (float*)(smem + SM_RED);

    if (bx < NPAIR) {
        // ================= qq via fp16 tensor cores =================
        int p = bx, ti = 0;
        while (p >= NTQ - ti) { p -= NTQ - ti; ti++; }
        int tj = ti + p;

        float4* sGi = (float4*)(smem + SM_GI);
        float4* sGj = (float4*)(smem + SM_GJ);

        // Stage fp16 alphas (8 halves per uint4).
        const uint4* alpha8 = (const uint4*)(g_alpha + (long long)b * KP * NC);
        for (int idx = tid; idx < 2 * QT * NC8; idx += 256) {
            int t = (idx >= QT * NC8);
            int l = idx - t * QT * NC8;
            int r = l / NC8, c8 = l - r * NC8;
            int g = (t ? tj : ti) * QT + r;
            uint4 v = (g < KP) ? alpha8[g * NC8 + c8] : make_uint4(0u, 0u, 0u, 0u);
            *(uint4*)(smem + (t ? SM_B : SM_A) + r * ROWB + c8 * 16) = v;
        }
        const float4* bb4 = (const float4*)pred_bboxes;
        for (int r = tid; r < QT; r += 256) {
            int gi = ti * QT + r;
            float4 u = (gi < KP) ? bb4[b * KP + gi] : make_float4(0.f, 0.f, 4.f, 4.f);
            sGi[r] = make_float4(u.x, u.y, u.z * u.z * 0.25f, u.w * u.w * 0.25f);
            int gj = tj * QT + r;
            float4 v = (gj < KP) ? bb4[b * KP + gj] : make_float4(0.f, 0.f, 4.f, 4.f);
            sGj[r] = make_float4(v.x, v.y, v.z * v.z * 0.25f, v.w * v.w * 0.25f);
        }
        __syncthreads();

        int wid = tid >> 5, lane = tid & 31;
        int g = lane >> 2, t = lane & 3;
        int mBase = (wid & 1) * 64;
        int nBase = (wid >> 1) * 32;

        // ldmatrix addressing: lanes 0-15 -> rows (k lo), 16-31 -> rows (k hi)
        int laneRow = lane & 15;
        int laneHi = (lane >> 4) & 1;
        uint32_t sbase = smem_u32(smem);
        uint32_t aAddr = sbase + SM_A + (mBase + laneRow) * ROWB + laneHi * 16;
        uint32_t bAddr = sbase + SM_B + (nBase + laneRow) * ROWB + laneHi * 16;

        uint32_t acc[4][4][2];
        #pragma unroll
        for (int mi = 0; mi < 4; mi++)
            #pragma unroll
            for (int ni = 0; ni < 4; ni++) { acc[mi][ni][0] = 0u; acc[mi][ni][1] = 0u; }

        #pragma unroll
        for (int k0 = 0; k0 < 5; k0++) {    // K=80, 16 per MMA
            uint32_t a[4][4], bf[4][2];
            #pragma unroll
            for (int mi = 0; mi < 4; mi++)
                LDSM_X4(a[mi][0], a[mi][1], a[mi][2], a[mi][3],
                        aAddr + mi * 16 * ROWB + k0 * 32);
            #pragma unroll
            for (int p2 = 0; p2 < 2; p2++) {
                uint32_t r0, r1, r2, r3;
                LDSM_X4(r0, r1, r2, r3, bAddr + p2 * 16 * ROWB + k0 * 32);
                bf[2 * p2][0] = r0; bf[2 * p2 + 1][0] = r1;
                bf[2 * p2][1] = r2; bf[2 * p2 + 1][1] = r3;
            }
            #pragma unroll
            for (int mi = 0; mi < 4; mi++)
                #pragma unroll
                for (int ni = 0; ni < 4; ni++)
                    MMA_F16ACC(acc[mi][ni], a[mi], bf[ni]);
        }

        // Epilogue: W[row][col] * gauss(row, col)
        float tsum = 0.f;
        #pragma unroll
        for (int mi = 0; mi < 4; mi++) {
            float4 P0 = sGi[mBase + mi * 16 + g];
            float4 P1 = sGi[mBase + mi * 16 + g + 8];
            #pragma unroll
            for (int ni = 0; ni < 4; ni++) {
                float4 Q0 = sGj[nBase + ni * 8 + t * 2];
                float4 Q1 = sGj[nBase + ni * 8 + t * 2 + 1];
                float2 w01 = __half22float2(*(const __half2*)&acc[mi][ni][0]);
                float2 w23 = __half22float2(*(const __half2*)&acc[mi][ni][1]);
                tsum = fmaf(w01.x, gauss_pair(P0, Q0), tsum);
                tsum = fmaf(w01.y, gauss_pair(P0, Q1), tsum);
                tsum = fmaf(w23.x, gauss_pair(P1, Q0), tsum);
                tsum = fmaf(w23.y, gauss_pair(P1, Q1), tsum);
            }
        }

        float s = warp_sum(tsum);
        if (lane == 0) red[wid] = s;
        __syncthreads();
        if (tid < 32) {
            float x = (tid < 8) ? red[tid] : 0.f;
            x = warp_sum(x);
            if (tid == 0) {
                float mult = (ti == tj) ? 1.f : 2.f;
                g_qq[b][bx] = (double)(x * mult);
            }
        }
    } else {
        // ================= pq / pp =================
        float4* sG = (float4*)(smem);
        int* sL = (int*)(smem + KG * 16);
        for (int i = tid; i < KG; i += 256) {
            float4 u = ((const float4*)gt_bboxes)[b * KG + i];
            sG[i] = make_float4(u.x, u.y, u.z * u.z * 0.25f, u.w * u.w * 0.25f);
            sL[i] = gt_labels[b * KG + i];
        }
        __syncthreads();

        float acc = 0.f;
        int chunk = bx - NPAIR;
        if (chunk < PQ_BLOCKS) {
            int j = chunk * 256 + tid;
            if (j < KP) {
                float4 u = ((const float4*)pred_bboxes)[b * KP + j];
                float4 Q = make_float4(u.x, u.y, u.z * u.z * 0.25f, u.w * u.w * 0.25f);
                const __half* arow = g_alpha + ((long long)b * KP + j) * NC;
                #pragma unroll 4
                for (int i = 0; i < KG; i++) {
                    float w = __half2float(__ldg(arow + sL[i]));
                    acc = fmaf(w, gauss_pair(sG[i], Q), acc);
                }
            }
        } else {
            for (int idx = tid; idx < KG * KG; idx += 256) {
                int i = idx / KG, j = idx - i * KG;
                if (sL[i] == sL[j]) acc += gauss_pair(sG[i], sG[j]);
            }
        }
        float s = warp_sum(acc);
        if ((tid & 31) == 0) red[tid >> 5] = s;
        __syncthreads();
        if (tid < 32) {
            float x = (tid < 8) ? red[tid] : 0.f;
            x = warp_sum(x);
            if (tid == 0) {
                if (chunk < PQ_BLOCKS) g_pq[b][chunk] = (double)x;
                else g_pp[b] = (double)x;
            }
        }
    }
}

// ---------------------------------------------------------------------------
// final: loss = -sum_b [2 log(pq_b) - log(pp_b) - log(qq_b)].
// One warp per image: lanes stride the 136 qq slots in parallel (5-load
// dependency chain instead of 141 serial loads).
// ---------------------------------------------------------------------------
__global__ __launch_bounds__(1024) void final_kernel(float* __restrict__ out) {
    __shared__ double sv[BS];
    int b = threadIdx.y;     // 32 warps, one per image
    int lane = threadIdx.x;

    double qq = 0.0;
    #pragma unroll
    for (int s = lane; s < NPAIR; s += 32) qq += g_qq[b][s];
    double pq = (lane < PQ_BLOCKS) ? g_pq[b][lane] : 0.0;

    qq = warp_sum_d(qq);
    pq = warp_sum_d(pq);

    if (lane == 0) {
        double pp = g_pp[b];
        sv[b] = 2.0 * log(pq) - log(pp) - log(qq);
    }
    __syncthreads();
    if (threadIdx.y == 0) {
        double v = sv[lane];
        v = warp_sum_d(v);
        if (lane == 0) out[0] = (float)(-v);
    }
}

extern "C" void kernel_launch(void* const* d_in, const int* in_sizes, int n_in,
                              void* d_out, int out_size) {
    const float* pred_bboxes = (const float*)d_in[0];
    const float* pred_labels = (const float*)d_in[1];
    const float* gt_bboxes   = (const float*)d_in[2];
    const int*   gt_labels   = (const int*)d_in[3];
    (void)in_sizes; (void)n_in; (void)out_size;

    cudaFuncSetAttribute(fused_kernel, cudaFuncAttributeMaxDynamicSharedMemorySize, SM_TOTAL);

    alpha_kernel<<<(BS * KP + 15) / 16, dim3(32, 8)>>>(pred_labels);
    fused_kernel<<<dim3(FUSED_X, BS), 256, SM_TOTAL>>>(pred_bboxes, gt_bboxes, gt_labels);
    final_kernel<<<1, dim3(32, 32)>>>((float*)d_out);
}

// round 15
// speedup vs baseline: 1.5215x; 1.5155x over previous
#include <cuda_runtime.h>
#include <cuda_fp16.h>
#include <cstdint>
#include <math.h>

#define BS 32
#define KP 1000
#define KG 100
#define NC 80
#define NC8 (NC/8)             // 10 uint4 (8 halves) per alpha row
#define QT 128                 // qq tile edge
#define NTQ 8                  // ceil(KP/QT)
#define NPAIR (NTQ*(NTQ+1)/2)  // 36 triangular tile pairs
#define PQ_BLOCKS 4
#define FUSED_X (NPAIR + PQ_BLOCKS + 1)
#define APITCH 88              // row pitch in halves (conflict-free, 16B-aligned rows)
#define ROWB (APITCH*2)        // 176 bytes per row

// dynamic smem layout (bytes)
#define SM_A     0
#define SM_B     (QT*ROWB)                // 22528
#define SM_GI    (2*QT*ROWB)              // 45056
#define SM_GJ    (SM_GI + QT*16)          // 47104
#define SM_RED   (SM_GJ + QT*16)          // 49152
#define SM_TOTAL (SM_RED + 64)            // 49216

__device__ __half g_alpha[BS*KP*NC];
__device__ double g_qq[BS][NPAIR];
__device__ double g_pq[BS][PQ_BLOCKS];
__device__ double g_pp[BS];

__device__ __forceinline__ uint32_t smem_u32(const void* p) {
    uint32_t a;
    asm("{ .reg .u64 t; cvta.to.shared.u64 t, %1; cvt.u32.u64 %0, t; }" : "=r"(a) : "l"(p));
    return a;
}

__device__ __forceinline__ float warp_sum(float v) {
    #pragma unroll
    for (int o = 16; o; o >>= 1) v += __shfl_xor_sync(0xffffffffu, v, o);
    return v;
}

// fp16-accumulator MMA: D,C are 2x f16x2 regs.
#define MMA_F16ACC(d, a, bq) \
    asm volatile("mma.sync.aligned.m16n8k16.row.col.f16.f16.f16.f16 " \
        "{%0,%1}, {%2,%3,%4,%5}, {%6,%7}, {%0,%1};" \
        : "+r"((d)[0]), "+r"((d)[1]) \
        : "r"((a)[0]), "r"((a)[1]), "r"((a)[2]), "r"((a)[3]), \
          "r"((bq)[0]), "r"((bq)[1]))

#define LDSM_X4(r0, r1, r2, r3, addr) \
    asm volatile("ldmatrix.sync.aligned.m8n8.x4.shared.b16 {%0,%1,%2,%3}, [%4];" \
        : "=r"(r0), "=r"(r1), "=r"(r2), "=r"(r3) : "r"(addr))

// Gaussian overlap (1/(2pi) cancels in the final log combination):
// g = exp2(C*q) * r,  C = -log2(e)/2,  q = (dx^2*sy + dy^2*sx)/(sx*sy),  r = rsqrt(sx*sy)
#define GAUSS_C (-0.7213475204444817f)
__device__ __forceinline__ float gauss_pair(float4 P, float4 Q) {
    float sx = P.z + Q.z, sy = P.w + Q.w;
    float dx = P.x - Q.x, dy = P.y - Q.y;
    float r = rsqrtf(sx * sy);
    float rrc = r * r * GAUSS_C;
    float q = fmaf(dy * dy, sx, dx * dx * sy) * rrc;
    return exp2f(q) * r;
}

// ---------------------------------------------------------------------------
// pred_alpha = sigmoid(logit[80]) * softmax(logit[0:80]); 4 rows per warp
// for MLP (kernel is DRAM-latency-bound). Logits ~N(0,1): exp() cannot
// overflow fp32, so no max-subtraction.
// ---------------------------------------------------------------------------
__global__ __launch_bounds__(256) void alpha_kernel(const float* __restrict__ labels) {
    int rowBase = (blockIdx.x * 8 + threadIdx.y) * 4;
    if (rowBase >= BS * KP) return;
    int lane = threadIdx.x;

    float e0[4], e1[4], e2[4], s[4], obj[4];
    #pragma unroll
    for (int rr = 0; rr < 4; rr++) {
        const float* L = labels + (long long)(rowBase + rr) * (NC + 1);
        e0[rr] = __expf(L[lane]);
        e1[rr] = __expf(L[lane + 32]);
        e2[rr] = (lane < 16) ? __expf(L[lane + 64]) : 0.f;
        obj[rr] = L[NC];
        s[rr] = e0[rr] + e1[rr] + e2[rr];
    }
    #pragma unroll
    for (int o = 16; o; o >>= 1) {
        #pragma unroll
        for (int rr = 0; rr < 4; rr++) s[rr] += __shfl_xor_sync(0xffffffffu, s[rr], o);
    }
    #pragma unroll
    for (int rr = 0; rr < 4; rr++) {
        float sig = 1.f / (1.f + __expf(-obj[rr]));
        float sc = sig / s[rr];
        __half* out = g_alpha + (long long)(rowBase + rr) * NC;
        out[lane]      = __float2half_rn(e0[rr] * sc);
        out[lane + 32] = __float2half_rn(e1[rr] * sc);
        if (lane < 16) out[lane + 64] = __float2half_rn(e2[rr] * sc);
    }
}

// ---------------------------------------------------------------------------
// Fused: bx < NPAIR -> qq tile pair via fp16 mma.sync (128x128x80, f16 accum)
//        bx < NPAIR+PQ_BLOCKS -> pq chunk ; else -> pp
// ---------------------------------------------------------------------------
__global__ __launch_bounds__(256, 3)
void fused_kernel(const float* __restrict__ pred_bboxes,
                  const float* __restrict__ gt_bboxes,
                  const int* __restrict__ gt_labels) {
    extern __shared__ char smem[];
    int b = blockIdx.y;
    int bx = blockIdx.x;
    int tid = threadIdx.x;
    float* red = (float*)(smem + SM_RED);

    if (bx < NPAIR) {
        // ================= qq via fp16 tensor cores =================
        int p = bx, ti = 0;
        while (p >= NTQ - ti) { p -= NTQ - ti; ti++; }
        int tj = ti + p;

        float4* sGi = (float4*)(smem + SM_GI);
        float4* sGj = (float4*)(smem + SM_GJ);

        // Stage fp16 alphas (8 halves per uint4).
        const uint4* alpha8 = (const uint4*)(g_alpha + (long long)b * KP * NC);
        for (int idx = tid; idx < 2 * QT * NC8; idx += 256) {
            int t = (idx >= QT * NC8);
            int l = idx - t * QT * NC8;
            int r = l / NC8, c8 = l - r * NC8;
            int g = (t ? tj : ti) * QT + r;
            uint4 v = (g < KP) ? alpha8[g * NC8 + c8] : make_uint4(0u, 0u, 0u, 0u);
            *(uint4*)(smem + (t ? SM_B : SM_A) + r * ROWB + c8 * 16) = v;
        }
        const float4* bb4 = (const float4*)pred_bboxes;
        for (int r = tid; r < QT; r += 256) {
            int gi = ti * QT + r;
            float4 u = (gi < KP) ? bb4[b * KP + gi] : make_float4(0.f, 0.f, 4.f, 4.f);
            sGi[r] = make_float4(u.x, u.y, u.z * u.z * 0.25f, u.w * u.w * 0.25f);
            int gj = tj * QT + r;
            float4 v = (gj < KP) ? bb4[b * KP + gj] : make_float4(0.f, 0.f, 4.f, 4.f);
            sGj[r] = make_float4(v.x, v.y, v.z * v.z * 0.25f, v.w * v.w * 0.25f);
        }
        __syncthreads();

        int wid = tid >> 5, lane = tid & 31;
        int g = lane >> 2, t = lane & 3;
        int mBase = (wid & 1) * 64;
        int nBase = (wid >> 1) * 32;

        // ldmatrix addressing: lanes 0-15 -> rows (k lo), 16-31 -> rows (k hi)
        int laneRow = lane & 15;
        int laneHi = (lane >> 4) & 1;
        uint32_t sbase = smem_u32(smem);
        uint32_t aAddr = sbase + SM_A + (mBase + laneRow) * ROWB + laneHi * 16;
        uint32_t bAddr = sbase + SM_B + (nBase + laneRow) * ROWB + laneHi * 16;

        uint32_t acc[4][4][2];
        #pragma unroll
        for (int mi = 0; mi < 4; mi++)
            #pragma unroll
            for (int ni = 0; ni < 4; ni++) { acc[mi][ni][0] = 0u; acc[mi][ni][1] = 0u; }

        #pragma unroll
        for (int k0 = 0; k0 < 5; k0++) {    // K=80, 16 per MMA
            uint32_t a[4][4], bf[4][2];
            #pragma unroll
            for (int mi = 0; mi < 4; mi++)
                LDSM_X4(a[mi][0], a[mi][1], a[mi][2], a[mi][3],
                        aAddr + mi * 16 * ROWB + k0 * 32);
            #pragma unroll
            for (int p2 = 0; p2 < 2; p2++) {
                uint32_t r0, r1, r2, r3;
                LDSM_X4(r0, r1, r2, r3, bAddr + p2 * 16 * ROWB + k0 * 32);
                bf[2 * p2][0] = r0; bf[2 * p2 + 1][0] = r1;
                bf[2 * p2][1] = r2; bf[2 * p2 + 1][1] = r3;
            }
            #pragma unroll
            for (int mi = 0; mi < 4; mi++)
                #pragma unroll
                for (int ni = 0; ni < 4; ni++)
                    MMA_F16ACC(acc[mi][ni], a[mi], bf[ni]);
        }

        // Epilogue: W[row][col] * gauss(row, col)
        float tsum = 0.f;
        #pragma unroll
        for (int mi = 0; mi < 4; mi++) {
            float4 P0 = sGi[mBase + mi * 16 + g];
            float4 P1 = sGi[mBase + mi * 16 + g + 8];
            #pragma unroll
            for (int ni = 0; ni < 4; ni++) {
                float4 Q0 = sGj[nBase + ni * 8 + t * 2];
                float4 Q1 = sGj[nBase + ni * 8 + t * 2 + 1];
                float2 w01 = __half22float2(*(const __half2*)&acc[mi][ni][0]);
                float2 w23 = __half22float2(*(const __half2*)&acc[mi][ni][1]);
                tsum = fmaf(w01.x, gauss_pair(P0, Q0), tsum);
                tsum = fmaf(w01.y, gauss_pair(P0, Q1), tsum);
                tsum = fmaf(w23.x, gauss_pair(P1, Q0), tsum);
                tsum = fmaf(w23.y, gauss_pair(P1, Q1), tsum);
            }
        }

        float s = warp_sum(tsum);
        if (lane == 0) red[wid] = s;
        __syncthreads();
        if (tid < 32) {
            float x = (tid < 8) ? red[tid] : 0.f;
            x = warp_sum(x);
            if (tid == 0) {
                float mult = (ti == tj) ? 1.f : 2.f;
                g_qq[b][bx] = (double)(x * mult);
            }
        }
    } else {
        // ================= pq / pp =================
        float4* sG = (float4*)(smem);
        int* sL = (int*)(smem + KG * 16);
        for (int i = tid; i < KG; i += 256) {
            float4 u = ((const float4*)gt_bboxes)[b * KG + i];
            sG[i] = make_float4(u.x, u.y, u.z * u.z * 0.25f, u.w * u.w * 0.25f);
            sL[i] = gt_labels[b * KG + i];
        }
        __syncthreads();

        float acc = 0.f;
        int chunk = bx - NPAIR;
        if (chunk < PQ_BLOCKS) {
            int j = chunk * 256 + tid;
            if (j < KP) {
                float4 u = ((const float4*)pred_bboxes)[b * KP + j];
                float4 Q = make_float4(u.x, u.y, u.z * u.z * 0.25f, u.w * u.w * 0.25f);
                const __half* arow = g_alpha + ((long long)b * KP + j) * NC;
                #pragma unroll 4
                for (int i = 0; i < KG; i++) {
                    float w = __half2float(__ldg(arow + sL[i]));
                    acc = fmaf(w, gauss_pair(sG[i], Q), acc);
                }
            }
        } else {
            for (int idx = tid; idx < KG * KG; idx += 256) {
                int i = idx / KG, j = idx - i * KG;
                if (sL[i] == sL[j]) acc += gauss_pair(sG[i], sG[j]);
            }
        }
        float s = warp_sum(acc);
        if ((tid & 31) == 0) red[tid >> 5] = s;
        __syncthreads();
        if (tid < 32) {
            float x = (tid < 8) ? red[tid] : 0.f;
            x = warp_sum(x);
            if (tid == 0) {
                if (chunk < PQ_BLOCKS) g_pq[b][chunk] = (double)x;
                else g_pp[b] = (double)x;
            }
        }
    }
}

// ---------------------------------------------------------------------------
// final: loss = -sum_b [2 log(pq_b) - log(pp_b) - log(qq_b)]
// ---------------------------------------------------------------------------
__global__ void final_kernel(float* __restrict__ out) {
    int b = threadIdx.x;  // 32 threads
    double pq = 0.0, qq = 0.0;
    #pragma unroll
    for (int s = 0; s < PQ_BLOCKS; s++) pq += g_pq[b][s];
    #pragma unroll
    for (int s = 0; s < NPAIR; s++) qq += g_qq[b][s];
    double pp = g_pp[b];
    double v = 2.0 * log(pq) - log(pp) - log(qq);
    #pragma unroll
    for (int o = 16; o; o >>= 1) v += __shfl_xor_sync(0xffffffffu, v, o);
    if (b == 0) out[0] = (float)(-v);
}

extern "C" void kernel_launch(void* const* d_in, const int* in_sizes, int n_in,
                              void* d_out, int out_size) {
    const float* pred_bboxes = (const float*)d_in[0];
    const float* pred_labels = (const float*)d_in[1];
    const float* gt_bboxes   = (const float*)d_in[2];
    const int*   gt_labels   = (const int*)d_in[3];
    (void)in_sizes; (void)n_in; (void)out_size;

    cudaFuncSetAttribute(fused_kernel, cudaFuncAttributeMaxDynamicSharedMemorySize, SM_TOTAL);

    alpha_kernel<<<(BS * KP + 31) / 32, dim3(32, 8)>>>(pred_labels);
    fused_kernel<<<dim3(FUSED_X, BS), 256, SM_TOTAL>>>(pred_bboxes, gt_bboxes, gt_labels);
    final_kernel<<<1, 32>>>((float*)d_out);
}